// round 8
// baseline (speedup 1.0000x reference)
#include <cuda_runtime.h>

#define NN_MAX 100000
#define CH 64
#define WEA 36
#define NBLK_E 444      // 148 SMs * 3 blocks

__device__ float g_PQ[(size_t)NN_MAX * 128];
__device__ int g_is64;

__device__ __forceinline__ unsigned f2tf32(float f) {
    unsigned u;
    asm("cvt.rna.tf32.f32 %0, %1;" : "=r"(u) : "f"(f));
    return u;
}

__device__ __forceinline__ void mma_tf32(float c[4], unsigned a0, unsigned a1,
                                         unsigned a2, unsigned a3,
                                         unsigned b0, unsigned b1) {
    asm volatile(
        "mma.sync.aligned.m16n8k8.row.col.f32.tf32.tf32.f32 "
        "{%0,%1,%2,%3}, {%4,%5,%6,%7}, {%8,%9}, {%0,%1,%2,%3};"
        : "+f"(c[0]), "+f"(c[1]), "+f"(c[2]), "+f"(c[3])
        : "r"(a0), "r"(a1), "r"(a2), "r"(a3), "r"(b0), "r"(b1));
}

// ---------------------------------------------------------------------------
__global__ void detect_kernel(const unsigned* __restrict__ ei_raw) {
    int t = threadIdx.x;
    unsigned nz = ei_raw[2 * t + 1] | ei_raw[2 * (t + 32) + 1];
    unsigned b = __ballot_sync(0xFFFFFFFFu, nz != 0u);
    if (t == 0) g_is64 = (b == 0u);
}

__global__ void zero_kernel(float4* __restrict__ out, int n4) {
    int i = blockIdx.x * blockDim.x + threadIdx.x;
    if (i < n4) out[i] = make_float4(0.f, 0.f, 0.f, 0.f);
}

// ---------------------------------------------------------------------------
// Node precompute, swizzled PQ store, uint4-paired B (LDS.128).
// ---------------------------------------------------------------------------
__global__ __launch_bounds__(256) void node_precompute(
    const float* __restrict__ x, const float* __restrict__ W1, int n_nodes) {
    __shared__ uint4 sBq[8 * 8 * 32];   // 32 KB: (s, tpair, lane)

    for (int idx = threadIdx.x; idx < 8 * 8 * 32; idx += 256) {
        int l = idx & 31, tp = (idx >> 5) & 7, s = idx >> 8;
        int g2 = l >> 2, q2 = l & 3;
        int n0 = 8 * (2 * tp) + g2, n1 = 8 * (2 * tp + 1) + g2;
        int k0 = 8 * s + q2, k1 = k0 + 4;
        float w00 = (n0 < 64) ? W1[(size_t)k0 * CH + n0] : W1[(size_t)(64 + k0) * CH + n0 - 64];
        float w10 = (n0 < 64) ? W1[(size_t)k1 * CH + n0] : W1[(size_t)(64 + k1) * CH + n0 - 64];
        float w01 = (n1 < 64) ? W1[(size_t)k0 * CH + n1] : W1[(size_t)(64 + k0) * CH + n1 - 64];
        float w11 = (n1 < 64) ? W1[(size_t)k1 * CH + n1] : W1[(size_t)(64 + k1) * CH + n1 - 64];
        sBq[idx] = make_uint4(f2tf32(w00), f2tf32(w10), f2tf32(w01), f2tf32(w11));
    }
    __syncthreads();

    const int warp = threadIdx.x >> 5, lane = threadIdx.x & 31;
    const int gr = lane >> 2, q = lane & 3;
    const int tile = blockIdx.x * 8 + warp;
    const int base = tile * 16;
    if (base >= n_nodes) return;
    const int r0 = base + gr, r1 = base + gr + 8;
    const bool v0 = r0 < n_nodes, v1 = r1 < n_nodes;

    float h[16][4];
#pragma unroll
    for (int t = 0; t < 16; t++)
        h[t][0] = h[t][1] = h[t][2] = h[t][3] = 0.f;

#pragma unroll
    for (int s = 0; s < 8; s++) {
        unsigned a0 = 0, a1 = 0, a2 = 0, a3 = 0;
        if (v0) {
            const float* r = x + (size_t)r0 * CH + 8 * s;
            a0 = f2tf32(r[q]); a2 = f2tf32(r[q + 4]);
        }
        if (v1) {
            const float* r = x + (size_t)r1 * CH + 8 * s;
            a1 = f2tf32(r[q]); a3 = f2tf32(r[q + 4]);
        }
#pragma unroll
        for (int tp = 0; tp < 8; tp++) {
            uint4 b = sBq[(s * 8 + tp) * 32 + lane];
            mma_tf32(h[2 * tp],     a0, a1, a2, a3, b.x, b.y);
            mma_tf32(h[2 * tp + 1], a0, a1, a2, a3, b.z, b.w);
        }
    }

#pragma unroll
    for (int t = 0; t < 16; t++) {
        int tp = t & 7, half = t >> 3;
        int it = tp >> 1, w = tp & 1;
        int off = half * 64 + (it * 4 + q) * 4 + w * 2;
        if (v0) *(float2*)&g_PQ[(size_t)r0 * 128 + off] = make_float2(h[t][0], h[t][1]);
        if (v1) *(float2*)&g_PQ[(size_t)r1 * 128 + off] = make_float2(h[t][2], h[t][3]);
    }
}

// ---------------------------------------------------------------------------
// Edge kernel: warp = 32 edges (two 16-edge subtiles), weight B-fragments
// shared across subtiles in both GEMMs. 128-thread blocks, >=3 blocks/SM.
// ---------------------------------------------------------------------------
__global__ __launch_bounds__(128, 3) void edge_kernel(
    const void* __restrict__ ei, const float* __restrict__ ea,
    const float* __restrict__ W1, const float* __restrict__ b1,
    const float* __restrict__ gamma, const float* __restrict__ beta,
    const float* __restrict__ W2, const float* __restrict__ b2,
    float* __restrict__ out, int n_edges) {
    __shared__ uint4 sW1q[4 * 4 * 32];        //  8 KB
    __shared__ uint4 sW2q[8 * 4 * 32];        // 16 KB
    __shared__ float sea[4][32 * WEA];        // 18 KB
    __shared__ float sb1[CH], sb2[CH], sgm[CH], sbt[CH];

    for (int idx = threadIdx.x; idx < 4 * 4 * 32; idx += 128) {
        int l = idx & 31, tp = (idx >> 5) & 3, s = idx >> 7;
        int g2 = l >> 2, q2 = l & 3;
        int n0 = 8 * (2 * tp) + g2, n1 = 8 * (2 * tp + 1) + g2;
        int k0 = 8 * s + q2, k1 = k0 + 4;
        sW1q[idx] = make_uint4(f2tf32(W1[(size_t)(128 + k0) * CH + n0]),
                               f2tf32(W1[(size_t)(128 + k1) * CH + n0]),
                               f2tf32(W1[(size_t)(128 + k0) * CH + n1]),
                               f2tf32(W1[(size_t)(128 + k1) * CH + n1]));
    }
    for (int idx = threadIdx.x; idx < 8 * 4 * 32; idx += 128) {
        int l = idx & 31, tp = (idx >> 5) & 3, s = idx >> 7;
        int g2 = l >> 2, q2 = l & 3;
        int n0 = 8 * (2 * tp) + g2, n1 = 8 * (2 * tp + 1) + g2;
        int k0 = 8 * s + q2, k1 = k0 + 4;
        sW2q[idx] = make_uint4(f2tf32(W2[(size_t)k0 * CH + n0]),
                               f2tf32(W2[(size_t)k1 * CH + n0]),
                               f2tf32(W2[(size_t)k0 * CH + n1]),
                               f2tf32(W2[(size_t)k1 * CH + n1]));
    }
    if (threadIdx.x < CH) {
        sb1[threadIdx.x] = b1[threadIdx.x];
        sb2[threadIdx.x] = b2[threadIdx.x];
        sgm[threadIdx.x] = gamma[threadIdx.x];
        sbt[threadIdx.x] = beta[threadIdx.x];
    }
    __syncthreads();

    const int warp = threadIdx.x >> 5, lane = threadIdx.x & 31;
    const int gr = lane >> 2;
    const int q  = lane & 3;
    const int is64 = g_is64;
    const unsigned FULL = 0xFFFFFFFFu;
    const int n_tiles = (n_edges + 31) / 32;
    float* mea = sea[warp];

    for (int tile = blockIdx.x * 4 + warp; tile < n_tiles;
         tile += gridDim.x * 4) {
        const int base = tile * 32;

        // ---- edge indices: lane e -> (i,j), distribute via shuffles ----
        int vi = 0, vj = 0;
        {
            int e = base + lane;
            if (e < n_edges) {
                if (is64) {
                    const long long* p = (const long long*)ei;
                    vi = (int)p[e]; vj = (int)p[(size_t)n_edges + e];
                } else {
                    const int* p = (const int*)ei;
                    vi = p[e]; vj = p[(size_t)n_edges + e];
                }
            }
        }
        const int r0 = gr, r1 = gr + 8, r2 = gr + 16, r3 = gr + 24;
        const int i0 = __shfl_sync(FULL, vi, r0), j0 = __shfl_sync(FULL, vj, r0);
        const int i1 = __shfl_sync(FULL, vi, r1), j1 = __shfl_sync(FULL, vj, r1);
        const int i2 = __shfl_sync(FULL, vi, r2), j2 = __shfl_sync(FULL, vj, r2);
        const int i3 = __shfl_sync(FULL, vi, r3), j3 = __shfl_sync(FULL, vj, r3);
        const bool v0 = (base + r0) < n_edges, v1 = (base + r1) < n_edges;
        const bool v2 = (base + r2) < n_edges, v3 = (base + r3) < n_edges;

        // ---- stage ea tile (32 rows) to smem ----
        __syncwarp();
        {
            const float* src = ea + (size_t)base * 32;
#pragma unroll
            for (int it = 0; it < 8; it++) {
                int idx = lane + 32 * it;
                int row = idx >> 3, c4 = idx & 7;
                float4 val = make_float4(0.f, 0.f, 0.f, 0.f);
                if (base + row < n_edges) val = *(const float4*)(src + row * 32 + c4 * 4);
                *(float4*)&mea[row * WEA + c4 * 4] = val;
            }
        }
        __syncwarp();

        // ---- GEMM1 (joint over both subtiles, shared B reads) ----
        float hA[8][4], hB[8][4];
#pragma unroll
        for (int t = 0; t < 8; t++) {
            hA[t][0] = hA[t][1] = hA[t][2] = hA[t][3] = 0.f;
            hB[t][0] = hB[t][1] = hB[t][2] = hB[t][3] = 0.f;
        }

#pragma unroll
        for (int s = 0; s < 4; s++) {
            unsigned aA0 = f2tf32(mea[r0 * WEA + 8 * s + q]);
            unsigned aA2 = f2tf32(mea[r0 * WEA + 8 * s + q + 4]);
            unsigned aA1 = f2tf32(mea[r1 * WEA + 8 * s + q]);
            unsigned aA3 = f2tf32(mea[r1 * WEA + 8 * s + q + 4]);
            unsigned aB0 = f2tf32(mea[r2 * WEA + 8 * s + q]);
            unsigned aB2 = f2tf32(mea[r2 * WEA + 8 * s + q + 4]);
            unsigned aB1 = f2tf32(mea[r3 * WEA + 8 * s + q]);
            unsigned aB3 = f2tf32(mea[r3 * WEA + 8 * s + q + 4]);
#pragma unroll
            for (int tp = 0; tp < 4; tp++) {
                uint4 b = sW1q[(s * 4 + tp) * 32 + lane];
                mma_tf32(hA[2 * tp],     aA0, aA1, aA2, aA3, b.x, b.y);
                mma_tf32(hA[2 * tp + 1], aA0, aA1, aA2, aA3, b.z, b.w);
                mma_tf32(hB[2 * tp],     aB0, aB1, aB2, aB3, b.x, b.y);
                mma_tf32(hB[2 * tp + 1], aB0, aB1, aB2, aB3, b.z, b.w);
            }
        }

        // ---- PQ gather (swizzled float4) ----
        {
            const float* Pa0 = g_PQ + (size_t)i0 * 128;
            const float* Qa0 = g_PQ + (size_t)j0 * 128 + 64;
            const float* Pa1 = g_PQ + (size_t)i1 * 128;
            const float* Qa1 = g_PQ + (size_t)j1 * 128 + 64;
            const float* Pb2 = g_PQ + (size_t)i2 * 128;
            const float* Qb2 = g_PQ + (size_t)j2 * 128 + 64;
            const float* Pb3 = g_PQ + (size_t)i3 * 128;
            const float* Qb3 = g_PQ + (size_t)j3 * 128 + 64;
#pragma unroll
            for (int it = 0; it < 4; it++) {
                int off = (it * 4 + q) * 4;
                int t0 = 2 * it, t1 = 2 * it + 1;
                int c0 = 8 * t0 + 2 * q, c1 = 8 * t1 + 2 * q;
                {
                    float4 pa = *(const float4*)&Pa0[off];
                    float4 qa = *(const float4*)&Qa0[off];
                    float4 pb = *(const float4*)&Pa1[off];
                    float4 qb = *(const float4*)&Qa1[off];
                    hA[t0][0] += pa.x + qa.x + sb1[c0];
                    hA[t0][1] += pa.y + qa.y + sb1[c0 + 1];
                    hA[t1][0] += pa.z + qa.z + sb1[c1];
                    hA[t1][1] += pa.w + qa.w + sb1[c1 + 1];
                    hA[t0][2] += pb.x + qb.x + sb1[c0];
                    hA[t0][3] += pb.y + qb.y + sb1[c0 + 1];
                    hA[t1][2] += pb.z + qb.z + sb1[c1];
                    hA[t1][3] += pb.w + qb.w + sb1[c1 + 1];
                }
                {
                    float4 pa = *(const float4*)&Pb2[off];
                    float4 qa = *(const float4*)&Qb2[off];
                    float4 pb = *(const float4*)&Pb3[off];
                    float4 qb = *(const float4*)&Qb3[off];
                    hB[t0][0] += pa.x + qa.x + sb1[c0];
                    hB[t0][1] += pa.y + qa.y + sb1[c0 + 1];
                    hB[t1][0] += pa.z + qa.z + sb1[c1];
                    hB[t1][1] += pa.w + qa.w + sb1[c1 + 1];
                    hB[t0][2] += pb.x + qb.x + sb1[c0];
                    hB[t0][3] += pb.y + qb.y + sb1[c0 + 1];
                    hB[t1][2] += pb.z + qb.z + sb1[c1];
                    hB[t1][3] += pb.w + qb.w + sb1[c1 + 1];
                }
            }
        }

        // ---- LayerNorm (4 row groups) ----
        float s0 = 0, ss0 = 0, s1 = 0, ss1 = 0, s2 = 0, ss2 = 0, s3 = 0, ss3 = 0;
#pragma unroll
        for (int t = 0; t < 8; t++) {
            s0 += hA[t][0] + hA[t][1]; ss0 += hA[t][0] * hA[t][0] + hA[t][1] * hA[t][1];
            s1 += hA[t][2] + hA[t][3]; ss1 += hA[t][2] * hA[t][2] + hA[t][3] * hA[t][3];
            s2 += hB[t][0] + hB[t][1]; ss2 += hB[t][0] * hB[t][0] + hB[t][1] * hB[t][1];
            s3 += hB[t][2] + hB[t][3]; ss3 += hB[t][2] * hB[t][2] + hB[t][3] * hB[t][3];
        }
#pragma unroll
        for (int o = 1; o <= 2; o <<= 1) {
            s0 += __shfl_xor_sync(FULL, s0, o); ss0 += __shfl_xor_sync(FULL, ss0, o);
            s1 += __shfl_xor_sync(FULL, s1, o); ss1 += __shfl_xor_sync(FULL, ss1, o);
            s2 += __shfl_xor_sync(FULL, s2, o); ss2 += __shfl_xor_sync(FULL, ss2, o);
            s3 += __shfl_xor_sync(FULL, s3, o); ss3 += __shfl_xor_sync(FULL, ss3, o);
        }
        float mu0 = s0 * (1.f / 64.f), rs0 = rsqrtf(ss0 * (1.f / 64.f) - mu0 * mu0 + 1e-5f);
        float mu1 = s1 * (1.f / 64.f), rs1 = rsqrtf(ss1 * (1.f / 64.f) - mu1 * mu1 + 1e-5f);
        float mu2 = s2 * (1.f / 64.f), rs2 = rsqrtf(ss2 * (1.f / 64.f) - mu2 * mu2 + 1e-5f);
        float mu3 = s3 * (1.f / 64.f), rs3 = rsqrtf(ss3 * (1.f / 64.f) - mu3 * mu3 + 1e-5f);

        // ---- gamma/beta + exact GELU ----
#pragma unroll
        for (int t = 0; t < 8; t++) {
            int c = 8 * t + 2 * q;
            float ga = sgm[c], gb = sgm[c + 1], ba = sbt[c], bb = sbt[c + 1];
            float g00 = (hA[t][0] - mu0) * rs0 * ga + ba;
            float g01 = (hA[t][1] - mu0) * rs0 * gb + bb;
            float g10 = (hA[t][2] - mu1) * rs1 * ga + ba;
            float g11 = (hA[t][3] - mu1) * rs1 * gb + bb;
            float g20 = (hB[t][0] - mu2) * rs2 * ga + ba;
            float g21 = (hB[t][1] - mu2) * rs2 * gb + bb;
            float g30 = (hB[t][2] - mu3) * rs3 * ga + ba;
            float g31 = (hB[t][3] - mu3) * rs3 * gb + bb;
            hA[t][0] = 0.5f * g00 * (1.f + erff(g00 * 0.7071067811865476f));
            hA[t][1] = 0.5f * g01 * (1.f + erff(g01 * 0.7071067811865476f));
            hA[t][2] = 0.5f * g10 * (1.f + erff(g10 * 0.7071067811865476f));
            hA[t][3] = 0.5f * g11 * (1.f + erff(g11 * 0.7071067811865476f));
            hB[t][0] = 0.5f * g20 * (1.f + erff(g20 * 0.7071067811865476f));
            hB[t][1] = 0.5f * g21 * (1.f + erff(g21 * 0.7071067811865476f));
            hB[t][2] = 0.5f * g30 * (1.f + erff(g30 * 0.7071067811865476f));
            hB[t][3] = 0.5f * g31 * (1.f + erff(g31 * 0.7071067811865476f));
        }

        // ---- GEMM2 (joint, shared B reads; hA[s]/hB[s] die per step) ----
        float mA[8][4], mB[8][4];
#pragma unroll
        for (int t = 0; t < 8; t++) {
            mA[t][0] = mA[t][1] = mA[t][2] = mA[t][3] = 0.f;
            mB[t][0] = mB[t][1] = mB[t][2] = mB[t][3] = 0.f;
        }

        const int srcA = (lane & ~3) | (q >> 1);
        const int srcB = srcA + 2;
#pragma unroll
        for (int s = 0; s < 8; s++) {
            float a00 = __shfl_sync(FULL, hA[s][0], srcA);
            float a01 = __shfl_sync(FULL, hA[s][1], srcA);
            float a10 = __shfl_sync(FULL, hA[s][2], srcA);
            float a11 = __shfl_sync(FULL, hA[s][3], srcA);
            float a20 = __shfl_sync(FULL, hA[s][0], srcB);
            float a21 = __shfl_sync(FULL, hA[s][1], srcB);
            float a30 = __shfl_sync(FULL, hA[s][2], srcB);
            float a31 = __shfl_sync(FULL, hA[s][3], srcB);
            unsigned aA0 = f2tf32((q & 1) ? a01 : a00);
            unsigned aA1 = f2tf32((q & 1) ? a11 : a10);
            unsigned aA2 = f2tf32((q & 1) ? a21 : a20);
            unsigned aA3 = f2tf32((q & 1) ? a31 : a30);
            float b00 = __shfl_sync(FULL, hB[s][0], srcA);
            float b01 = __shfl_sync(FULL, hB[s][1], srcA);
            float b10 = __shfl_sync(FULL, hB[s][2], srcA);
            float b11 = __shfl_sync(FULL, hB[s][3], srcA);
            float b20 = __shfl_sync(FULL, hB[s][0], srcB);
            float b21 = __shfl_sync(FULL, hB[s][1], srcB);
            float b30 = __shfl_sync(FULL, hB[s][2], srcB);
            float b31 = __shfl_sync(FULL, hB[s][3], srcB);
            unsigned aB0 = f2tf32((q & 1) ? b01 : b00);
            unsigned aB1 = f2tf32((q & 1) ? b11 : b10);
            unsigned aB2 = f2tf32((q & 1) ? b21 : b20);
            unsigned aB3 = f2tf32((q & 1) ? b31 : b30);
#pragma unroll
            for (int tp = 0; tp < 4; tp++) {
                uint4 b = sW2q[(s * 4 + tp) * 32 + lane];
                mma_tf32(mA[2 * tp],     aA0, aA1, aA2, aA3, b.x, b.y);
                mma_tf32(mA[2 * tp + 1], aA0, aA1, aA2, aA3, b.z, b.w);
                mma_tf32(mB[2 * tp],     aB0, aB1, aB2, aB3, b.x, b.y);
                mma_tf32(mB[2 * tp + 1], aB0, aB1, aB2, aB3, b.z, b.w);
            }
        }

        // ---- v4 scatter-add (both subtiles) ----
#pragma unroll
        for (int t = 0; t < 8; t++) {
            int c = 8 * t + 2 * q;
            float sb2a = sb2[c], sb2b = sb2[c + 1];
            {
                float p0 = mA[t][0] + sb2a, p1 = mA[t][1] + sb2b;
                float e0 = __shfl_xor_sync(FULL, p0, 1);
                float e1 = __shfl_xor_sync(FULL, p1, 1);
                float q2v = mA[t][2] + sb2a, q3v = mA[t][3] + sb2b;
                float e2 = __shfl_xor_sync(FULL, q2v, 1);
                float e3 = __shfl_xor_sync(FULL, q3v, 1);
                if ((q & 1) == 0) {
                    if (v0) {
                        float* dst = out + (size_t)j0 * CH + 8 * t + 2 * q;
                        asm volatile("red.global.add.v4.f32 [%0], {%1,%2,%3,%4};"
                                     :: "l"(dst), "f"(p0), "f"(p1), "f"(e0), "f"(e1)
                                     : "memory");
                    }
                } else {
                    if (v1) {
                        float* dst = out + (size_t)j1 * CH + 8 * t + 2 * (q - 1);
                        asm volatile("red.global.add.v4.f32 [%0], {%1,%2,%3,%4};"
                                     :: "l"(dst), "f"(e2), "f"(e3), "f"(q2v), "f"(q3v)
                                     : "memory");
                    }
                }
            }
            {
                float p0 = mB[t][0] + sb2a, p1 = mB[t][1] + sb2b;
                float e0 = __shfl_xor_sync(FULL, p0, 1);
                float e1 = __shfl_xor_sync(FULL, p1, 1);
                float q2v = mB[t][2] + sb2a, q3v = mB[t][3] + sb2b;
                float e2 = __shfl_xor_sync(FULL, q2v, 1);
                float e3 = __shfl_xor_sync(FULL, q3v, 1);
                if ((q & 1) == 0) {
                    if (v2) {
                        float* dst = out + (size_t)j2 * CH + 8 * t + 2 * q;
                        asm volatile("red.global.add.v4.f32 [%0], {%1,%2,%3,%4};"
                                     :: "l"(dst), "f"(p0), "f"(p1), "f"(e0), "f"(e1)
                                     : "memory");
                    }
                } else {
                    if (v3) {
                        float* dst = out + (size_t)j3 * CH + 8 * t + 2 * (q - 1);
                        asm volatile("red.global.add.v4.f32 [%0], {%1,%2,%3,%4};"
                                     :: "l"(dst), "f"(e2), "f"(e3), "f"(q2v), "f"(q3v)
                                     : "memory");
                    }
                }
            }
        }
    }
}

// ---------------------------------------------------------------------------
extern "C" void kernel_launch(void* const* d_in, const int* in_sizes, int n_in,
                              void* d_out, int out_size) {
    const float* x     = (const float*)d_in[0];
    const void*  ei    = d_in[1];
    const float* ea    = (const float*)d_in[2];
    const float* W1    = (const float*)d_in[3];
    const float* b1    = (const float*)d_in[4];
    const float* gamma = (const float*)d_in[5];
    const float* beta  = (const float*)d_in[6];
    const float* W2    = (const float*)d_in[7];
    const float* b2    = (const float*)d_in[8];
    float* out = (float*)d_out;

    int n_nodes = in_sizes[0] / CH;
    int n_edges = in_sizes[2] / 32;

    detect_kernel<<<1, 32>>>((const unsigned*)ei);

    int n4 = out_size / 4;
    zero_kernel<<<(n4 + 255) / 256, 256>>>((float4*)out, n4);

    int n_node_tiles = (n_nodes + 15) / 16;
    node_precompute<<<(n_node_tiles + 7) / 8, 256>>>(x, W1, n_nodes);

    edge_kernel<<<NBLK_E, 128>>>(ei, ea, W1, b1, gamma, beta, W2, b2, out, n_edges);
}